// round 1
// baseline (speedup 1.0000x reference)
#include <cuda_runtime.h>
#include <cstdint>

#define B_  4
#define S_  2048
#define D_  1024
#define H_  16
#define DH  64

// Scratch (device globals -- no allocations allowed)
__device__ float g_q[(size_t)B_*H_*S_*DH];     // 33.5 MB
__device__ float g_k[(size_t)B_*H_*S_*DH];     // 33.5 MB
__device__ float g_ksum[B_*H_*DH];

// ---------------------------------------------------------------------------
// Kernel 1: fused q/k projection  C[m,n] = x[m,:] . W[n,:] + bias[n]
// M=8192, N=2048, K=1024.  Tile 128x128, BK=16, 256 threads, 8x8 microtile.
// Scatter epilogue into g_q / g_k in [B,H,S,dh] layout.
// ---------------------------------------------------------------------------
__global__ __launch_bounds__(256) void proj_kernel(
    const float* __restrict__ x, const float* __restrict__ W,
    const float* __restrict__ bias)
{
    __shared__ float As[16][132];   // As[k][m]
    __shared__ float Bs[16][132];   // Bs[k][n]

    const int tid = threadIdx.x;
    const int m0 = blockIdx.y * 128;
    const int n0 = blockIdx.x * 128;
    const int tx = tid & 15, ty = tid >> 4;
    const int rm = ty * 8, rn = tx * 8;

    float acc[8][8];
#pragma unroll
    for (int i = 0; i < 8; i++)
#pragma unroll
        for (int j = 0; j < 8; j++) acc[i][j] = 0.f;

    const int row  = tid >> 1;       // 0..127
    const int kk   = (tid & 1) * 8;  // 0 or 8

    for (int k0 = 0; k0 < D_; k0 += 16) {
        const float* ax = x + (size_t)(m0 + row) * D_ + k0 + kk;
        const float* bw = W + (size_t)(n0 + row) * D_ + k0 + kk;
        float4 a0 = *(const float4*)(ax);
        float4 a1 = *(const float4*)(ax + 4);
        float4 b0 = *(const float4*)(bw);
        float4 b1 = *(const float4*)(bw + 4);
        As[kk+0][row] = a0.x; As[kk+1][row] = a0.y; As[kk+2][row] = a0.z; As[kk+3][row] = a0.w;
        As[kk+4][row] = a1.x; As[kk+5][row] = a1.y; As[kk+6][row] = a1.z; As[kk+7][row] = a1.w;
        Bs[kk+0][row] = b0.x; Bs[kk+1][row] = b0.y; Bs[kk+2][row] = b0.z; Bs[kk+3][row] = b0.w;
        Bs[kk+4][row] = b1.x; Bs[kk+5][row] = b1.y; Bs[kk+6][row] = b1.z; Bs[kk+7][row] = b1.w;
        __syncthreads();

#pragma unroll 4
        for (int k = 0; k < 16; k++) {
            float af[8], bf[8];
            *(float4*)&af[0] = *(const float4*)&As[k][rm];
            *(float4*)&af[4] = *(const float4*)&As[k][rm + 4];
            *(float4*)&bf[0] = *(const float4*)&Bs[k][rn];
            *(float4*)&bf[4] = *(const float4*)&Bs[k][rn + 4];
#pragma unroll
            for (int i = 0; i < 8; i++)
#pragma unroll
                for (int j = 0; j < 8; j++)
                    acc[i][j] += af[i] * bf[j];
        }
        __syncthreads();
    }

    // Epilogue: n = h*128 + d*2 + c  (c: 0=q, 1=k)
#pragma unroll
    for (int i = 0; i < 8; i++) {
        const int m = m0 + rm + i;
        const int bb = m >> 11;          // / 2048
        const int s  = m & 2047;
#pragma unroll
        for (int j = 0; j < 8; j++) {
            const int n = n0 + rn + j;
            const float v = acc[i][j] + bias[n];
            const int hh = n >> 7;
            const int d  = (n >> 1) & 63;
            const size_t idx = (((size_t)bb * H_ + hh) * S_ + s) * DH + d;
            if (n & 1) g_k[idx] = v; else g_q[idx] = v;
        }
    }
}

// ---------------------------------------------------------------------------
// Kernel 2: ksum[b,h,d] = sum_s k[b,h,s,d]
// ---------------------------------------------------------------------------
__global__ __launch_bounds__(256) void ksum_kernel()
{
    __shared__ float red[256];
    const int bh = blockIdx.x;
    const int t = threadIdx.x;
    const int d = t & 63;
    const int chunk = t >> 6;            // 0..3
    const float* base = g_k + (size_t)bh * S_ * DH;
    float s = 0.f;
    const int j0 = chunk * (S_ / 4), j1 = j0 + (S_ / 4);
    for (int j = j0; j < j1; j++) s += base[(size_t)j * DH + d];
    red[t] = s;
    __syncthreads();
    if (t < 64)
        g_ksum[bh * DH + t] = red[t] + red[64 + t] + red[128 + t] + red[192 + t];
}

// ---------------------------------------------------------------------------
// Kernel 3: fused attention per (b, h, q-tile of 128 rows).
//   mean_i = (scale/S) * q_i . ksum
//   out    = selu(scale*QK^T - mean) @ V * S^-0.5,  V read directly from x.
// Dynamic smem layout (floats):
//   qs [64][132]  (q transposed, [d][row])
//   ks [64][68]   (k transposed, [d][j])
//   vs [64][68]   ([j][d])
//   as [64][132]  (activation, [j][row])
// ---------------------------------------------------------------------------
#define BM 128
#define BN 64

__global__ __launch_bounds__(256) void attn_kernel(
    const float* __restrict__ x, float* __restrict__ out)
{
    extern __shared__ float smem[];
    float* qs  = smem;                 // 64*132 = 8448
    float* ks  = qs + 64 * 132;        // 64*68  = 4352
    float* vs  = ks + 64 * 68;         // 64*68  = 4352
    float* as_ = vs + 64 * 68;         // 64*132 = 8448   total 25600 floats

    const int b  = blockIdx.z;
    const int h  = blockIdx.y;
    const int s0 = blockIdx.x * BM;
    const int tid = threadIdx.x;
    const int tx = tid & 15, ty = tid >> 4;
    const int r0 = ty * 8;             // 8 rows per thread
    const int c0 = tx * 4;             // 4 cols per thread

    const size_t bh = (size_t)b * H_ + h;
    const float* qg = g_q + bh * S_ * DH;
    const float* kg = g_k + bh * S_ * DH;
    const float* ksum = g_ksum + bh * DH;

    // ---- load Q tile transposed ----
    {
        const int row  = tid >> 1;
        const int dblk = (tid & 1) * 32;
        const float* src = qg + (size_t)(s0 + row) * DH + dblk;
#pragma unroll
        for (int v4 = 0; v4 < 8; v4++) {
            float4 q4 = *(const float4*)(src + v4 * 4);
            const int d = dblk + v4 * 4;
            qs[(d + 0) * 132 + row] = q4.x;
            qs[(d + 1) * 132 + row] = q4.y;
            qs[(d + 2) * 132 + row] = q4.z;
            qs[(d + 3) * 132 + row] = q4.w;
        }
    }
    __syncthreads();

    const float SCALE = 0.125f;                       // dh^-0.5
    // ---- per-row mean via ksum trick ----
    float mrow[8];
#pragma unroll
    for (int i = 0; i < 8; i++) mrow[i] = 0.f;
    for (int d = 0; d < DH; d++) {
        const float kv = ksum[d];
#pragma unroll
        for (int i = 0; i < 8; i++) mrow[i] += qs[d * 132 + r0 + i] * kv;
    }
#pragma unroll
    for (int i = 0; i < 8; i++) mrow[i] *= SCALE * (1.f / (float)S_);

    float acc[8][4];
#pragma unroll
    for (int i = 0; i < 8; i++)
#pragma unroll
        for (int c = 0; c < 4; c++) acc[i][c] = 0.f;

    const int jrow = tid >> 2;          // 0..63
    const int jd   = (tid & 3) * 16;    // 0,16,32,48

    for (int j0 = 0; j0 < S_; j0 += BN) {
        // ---- load K tile transposed + V tile (V == x slice) ----
        const float* ksrc = kg + (size_t)(j0 + jrow) * DH + jd;
        const float* vsrc = x + ((size_t)b * S_ + j0 + jrow) * D_ + h * DH + jd;
#pragma unroll
        for (int v4 = 0; v4 < 4; v4++) {
            float4 k4 = *(const float4*)(ksrc + v4 * 4);
            const int d = jd + v4 * 4;
            ks[(d + 0) * 68 + jrow] = k4.x;
            ks[(d + 1) * 68 + jrow] = k4.y;
            ks[(d + 2) * 68 + jrow] = k4.z;
            ks[(d + 3) * 68 + jrow] = k4.w;
            *(float4*)(vs + jrow * 68 + d) = *(const float4*)(vsrc + v4 * 4);
        }
        __syncthreads();

        // ---- P = Q K^T (8x4 per thread) ----
        float p[8][4];
#pragma unroll
        for (int i = 0; i < 8; i++)
#pragma unroll
            for (int c = 0; c < 4; c++) p[i][c] = 0.f;

#pragma unroll 4
        for (int d = 0; d < DH; d++) {
            float af[8], bf[4];
            *(float4*)&af[0] = *(const float4*)&qs[d * 132 + r0];
            *(float4*)&af[4] = *(const float4*)&qs[d * 132 + r0 + 4];
            *(float4*)&bf[0] = *(const float4*)&ks[d * 68 + c0];
#pragma unroll
            for (int i = 0; i < 8; i++)
#pragma unroll
                for (int c = 0; c < 4; c++)
                    p[i][c] += af[i] * bf[c];
        }

        // ---- selu(scale*p - mean) -> as_ (transposed [j][row]) ----
#pragma unroll
        for (int c = 0; c < 4; c++) {
#pragma unroll
            for (int i = 0; i < 8; i++) {
                const float s = p[i][c] * SCALE - mrow[i];
                const float r = (s > 0.f)
                    ? 1.0507009873554805f * s
                    : 1.7580993408473766f * (__expf(s) - 1.f);
                as_[(c0 + c) * 132 + r0 + i] = r;
            }
        }
        __syncthreads();

        // ---- acc += A @ V ----
#pragma unroll 4
        for (int j = 0; j < BN; j++) {
            float af[8], vf[4];
            *(float4*)&af[0] = *(const float4*)&as_[j * 132 + r0];
            *(float4*)&af[4] = *(const float4*)&as_[j * 132 + r0 + 4];
            *(float4*)&vf[0] = *(const float4*)&vs[j * 68 + c0];
#pragma unroll
            for (int i = 0; i < 8; i++)
#pragma unroll
                for (int c = 0; c < 4; c++)
                    acc[i][c] += af[i] * vf[c];
        }
        __syncthreads();
    }

    // ---- epilogue: out[b, s, h*64 + d] = acc * S^-0.5 ----
    const float OS = 0.022097086912079608f;   // 2048^-0.5
#pragma unroll
    for (int i = 0; i < 8; i++) {
        float* dst = out + ((size_t)b * S_ + s0 + r0 + i) * D_ + h * DH + c0;
        float4 o4 = make_float4(acc[i][0] * OS, acc[i][1] * OS,
                                acc[i][2] * OS, acc[i][3] * OS);
        *(float4*)dst = o4;
    }
}

// ---------------------------------------------------------------------------
extern "C" void kernel_launch(void* const* d_in, const int* in_sizes, int n_in,
                              void* d_out, int out_size)
{
    const float* x    = (const float*)d_in[0];
    const float* W    = (const float*)d_in[1];
    const float* bias = (const float*)d_in[2];
    float* out = (float*)d_out;

    // 25600 floats = 102400 B dynamic smem for attention (idempotent, capture-safe)
    cudaFuncSetAttribute(attn_kernel,
                         cudaFuncAttributeMaxDynamicSharedMemorySize, 102400);

    dim3 pg(D_ * 2 / 128, (B_ * S_) / 128);          // (16, 64)
    proj_kernel<<<pg, 256>>>(x, W, bias);

    ksum_kernel<<<B_ * H_, 256>>>();

    dim3 ag(S_ / BM, H_, B_);                        // (16, 16, 4)
    attn_kernel<<<ag, 256, 102400>>>(x, out);
}